// round 3
// baseline (speedup 1.0000x reference)
#include <cuda_runtime.h>
#include <math.h>

#define BSZ 2
#define SEQ 2048
#define DMODEL 4096
#define NH 32
#define NKV 8
#define NREP 4
#define HD 128

#define QSTR (NH * HD)    // 4096
#define KSTR (NKV * HD)   // 1024

// Scratch (device globals: allocation-guard safe)
__device__ float g_Q[BSZ * SEQ * NH * HD];
__device__ float g_K[BSZ * SEQ * NKV * HD];
__device__ float g_V[BSZ * SEQ * NKV * HD];
__device__ float g_O[BSZ * SEQ * NH * HD];

// ---------------------------------------------------------------------------
// GEMM: C[M,N] = A[M,K] @ B[K,N], row-major. M%64==0, N%64==0, K%32==0.
// 64x64 tile, BK=32, 256 threads, 4x4 outputs per thread.
// ---------------------------------------------------------------------------
__global__ __launch_bounds__(256) void gemm_tile(
    const float* __restrict__ A, const float* __restrict__ B,
    float* __restrict__ C, int M, int N, int K)
{
    __shared__ float As[64][33];   // As[m][k]
    __shared__ float Bs[32][65];   // Bs[k][n]

    const int tid = threadIdx.x;
    const int tr  = tid / 16;
    const int tc  = tid % 16;
    const int bm  = blockIdx.y * 64;
    const int bn  = blockIdx.x * 64;

    float acc[4][4];
#pragma unroll
    for (int i = 0; i < 4; i++)
#pragma unroll
        for (int j = 0; j < 4; j++) acc[i][j] = 0.0f;

    for (int k0 = 0; k0 < K; k0 += 32) {
        for (int i = tid; i < 512; i += 256) {
            int r = i / 8;
            int c = (i % 8) * 4;
            float4 v = *(const float4*)(A + (size_t)(bm + r) * K + k0 + c);
            As[r][c + 0] = v.x;
            As[r][c + 1] = v.y;
            As[r][c + 2] = v.z;
            As[r][c + 3] = v.w;
        }
        for (int i = tid; i < 512; i += 256) {
            int r = i / 16;
            int c = (i % 16) * 4;
            float4 v = *(const float4*)(B + (size_t)(k0 + r) * N + bn + c);
            Bs[r][c + 0] = v.x;
            Bs[r][c + 1] = v.y;
            Bs[r][c + 2] = v.z;
            Bs[r][c + 3] = v.w;
        }
        __syncthreads();

#pragma unroll
        for (int kk = 0; kk < 32; kk++) {
            float a[4], bb[4];
#pragma unroll
            for (int i = 0; i < 4; i++) a[i]  = As[tr * 4 + i][kk];
#pragma unroll
            for (int j = 0; j < 4; j++) bb[j] = Bs[kk][tc * 4 + j];
#pragma unroll
            for (int i = 0; i < 4; i++)
#pragma unroll
                for (int j = 0; j < 4; j++) acc[i][j] += a[i] * bb[j];
        }
        __syncthreads();
    }

#pragma unroll
    for (int i = 0; i < 4; i++)
#pragma unroll
        for (int j = 0; j < 4; j++)
            C[(size_t)(bm + tr * 4 + i) * N + bn + tc * 4 + j] = acc[i][j];
}

// ---------------------------------------------------------------------------
// RoPE in place, ACCURATE trig (immune to --use_fast_math MUFU substitution).
// The reference computes ang = fp32(s) * fp32(inv) and takes fp32 cos/sin of
// that angle with exact argument reduction. We reproduce: inv in double ->
// round to fp32 -> fp32 product -> double-precision sincos of the fp32 angle.
// grid = (BSZ*SEQ, nheads), block = 64 threads (one per rotation pair).
// ---------------------------------------------------------------------------
__global__ __launch_bounds__(64) void rope2(float* __restrict__ x, int nheads)
{
    const int pair = threadIdx.x;          // 0..63
    const int h    = blockIdx.y;
    const int row  = blockIdx.x;           // b*SEQ + s
    const int s    = row % SEQ;

    // inv = 10000^(-pair/64), computed in double, rounded to fp32
    double inv_d = exp(-(double)pair * (1.0 / 64.0) * log(10000.0));
    float  inv_f = (float)inv_d;
    float  ang_f = (float)s * inv_f;       // fp32 angle, matches reference

    double cd = cos((double)ang_f);
    double sd = sin((double)ang_f);
    float  c  = (float)cd;
    float  sn = (float)sd;

    float* p = x + (size_t)row * (nheads * HD) + h * HD + pair * 2;
    float x0 = p[0];
    float x1 = p[1];
    p[0] = x0 * c - x1 * sn;
    p[1] = x0 * sn + x1 * c;
}

// ---------------------------------------------------------------------------
// Naive causal attention, two-pass softmax. One block per (query pos, head).
// block = 128 threads. grid = (SEQ, NH, BSZ).
// ---------------------------------------------------------------------------
__global__ __launch_bounds__(128) void attn_naive(
    const float* __restrict__ Q, const float* __restrict__ K,
    const float* __restrict__ V, float* __restrict__ O)
{
    __shared__ float sp[SEQ];     // scores / probs for this row
    __shared__ float qs[HD];      // query vector (pre-scaled)
    __shared__ float wred[4];     // warp reduction scratch

    const int t    = threadIdx.x;       // 0..127
    const int lane = t & 31;
    const int warp = t >> 5;
    const int s    = blockIdx.x;        // query position
    const int h    = blockIdx.y;        // query head
    const int b    = blockIdx.z;
    const int g    = h / NREP;          // kv head

    const float scale = 0.08838834764831845f;   // 1/sqrt(128)

    const float* q  = Q + ((size_t)b * SEQ + s) * QSTR + h * HD;
    const float* Kb = K + (size_t)b * SEQ * KSTR + g * HD;
    const float* Vb = V + (size_t)b * SEQ * KSTR + g * HD;

    qs[t] = q[t] * scale;
    __syncthreads();

    const int nk = s + 1;     // causal: keys 0..s inclusive

    // Pass 1: scores + local max
    float lmax = -INFINITY;
    for (int k = t; k < nk; k += 128) {
        const float* kr = Kb + (size_t)k * KSTR;
        float d = 0.0f;
#pragma unroll 8
        for (int e = 0; e < HD; e++) d += qs[e] * kr[e];
        sp[k] = d;
        if (d > lmax) lmax = d;
    }
#pragma unroll
    for (int o = 16; o > 0; o >>= 1)
        lmax = fmaxf(lmax, __shfl_xor_sync(0xFFFFFFFFu, lmax, o));
    if (lane == 0) wred[warp] = lmax;
    __syncthreads();
    float m = fmaxf(fmaxf(wred[0], wred[1]), fmaxf(wred[2], wred[3]));
    __syncthreads();

    // Pass 2: exponentiate + local sum
    float lsum = 0.0f;
    for (int k = t; k < nk; k += 128) {
        float e = expf(sp[k] - m);
        sp[k] = e;
        lsum += e;
    }
#pragma unroll
    for (int o = 16; o > 0; o >>= 1)
        lsum += __shfl_xor_sync(0xFFFFFFFFu, lsum, o);
    if (lane == 0) wred[warp] = lsum;
    __syncthreads();
    float l = wred[0] + wred[1] + wred[2] + wred[3];
    __syncthreads();

    // PV: thread t owns output dim t
    float acc = 0.0f;
    for (int k = 0; k < nk; k++)
        acc += sp[k] * Vb[(size_t)k * KSTR + t];

    O[((size_t)b * SEQ + s) * QSTR + h * HD + t] = acc / l;
}

// ---------------------------------------------------------------------------
extern "C" void kernel_launch(void* const* d_in, const int* in_sizes, int n_in,
                              void* d_out, int out_size)
{
    // Input mapping with runtime dispatch on the in_sizes signature.
    // Expected sizes: x=16777216, wq=16777216, wk=4194304, wv=4194304,
    //                 wo=16777216, start_pos=1, inference=1
    const float *x, *wq, *wk, *wv, *wo;
    if (n_in >= 7 && in_sizes[0] == 1 && in_sizes[1] == 1) {
        if (in_sizes[2] == 16777216) {
            // scalars-first, then declaration order: sp, inf, x, wq, wk, wv, wo
            x  = (const float*)d_in[2];
            wq = (const float*)d_in[3];
            wk = (const float*)d_in[4];
            wv = (const float*)d_in[5];
            wo = (const float*)d_in[6];
        } else {
            // alphabetical: inference, start_pos, wk, wo, wq, wv, x
            wk = (const float*)d_in[2];
            wo = (const float*)d_in[3];
            wq = (const float*)d_in[4];
            wv = (const float*)d_in[5];
            x  = (const float*)d_in[6];
        }
    } else {
        // declaration order: x, wq, wk, wv, wo, [start_pos, inference]
        x  = (const float*)d_in[0];
        wq = (const float*)d_in[1];
        wk = (const float*)d_in[2];
        wv = (const float*)d_in[3];
        wo = (const float*)d_in[4];
    }
    float* out = (float*)d_out;

    float* Qp; cudaGetSymbolAddress((void**)&Qp, g_Q);
    float* Kp; cudaGetSymbolAddress((void**)&Kp, g_K);
    float* Vp; cudaGetSymbolAddress((void**)&Vp, g_V);
    float* Op; cudaGetSymbolAddress((void**)&Op, g_O);

    const int M = BSZ * SEQ;   // 4096

    // QKV projections
    gemm_tile<<<dim3(DMODEL / 64, M / 64), 256>>>(x, wq, Qp, M, DMODEL, DMODEL);
    gemm_tile<<<dim3(KSTR / 64, M / 64), 256>>>(x, wk, Kp, M, KSTR, DMODEL);
    gemm_tile<<<dim3(KSTR / 64, M / 64), 256>>>(x, wv, Vp, M, KSTR, DMODEL);

    // RoPE (in place on Q and K) — accurate trig
    rope2<<<dim3(M, NH), 64>>>(Qp, NH);
    rope2<<<dim3(M, NKV), 64>>>(Kp, NKV);

    // Causal attention
    attn_naive<<<dim3(SEQ, NH, BSZ), 128>>>(Qp, Kp, Vp, Op);

    // Output projection
    gemm_tile<<<dim3(DMODEL / 64, M / 64), 256>>>(Op, wo, out, M, DMODEL, DMODEL);
}

// round 4
// speedup vs baseline: 4.1818x; 4.1818x over previous
#include <cuda_runtime.h>
#include <math.h>

#define BSZ 2
#define SEQ 2048
#define DMODEL 4096
#define NH 32
#define NKV 8
#define NREP 4
#define HD 128

#define QSTR (NH * HD)    // 4096
#define KSTR (NKV * HD)   // 1024

// Scratch (device globals: allocation-guard safe)
__device__ float g_Q[BSZ * SEQ * NH * HD];
__device__ float g_K[BSZ * SEQ * NKV * HD];
__device__ float g_V[BSZ * SEQ * NKV * HD];
__device__ float g_O[BSZ * SEQ * NH * HD];

// ---------------------------------------------------------------------------
// GEMM: C[M,N] = A[M,K] @ B[K,N], row-major. M%128==0, N%128==0, K%16==0.
// 128x128 tile, BK=16, 256 threads, 8x8 per thread, register prefetch.
// ---------------------------------------------------------------------------
#define APAD 132   // row stride (floats) for As/Bs; 132*4B = 528 = 33*16 (16B-aligned rows)

__global__ __launch_bounds__(256) void gemm128(
    const float* __restrict__ A, const float* __restrict__ B,
    float* __restrict__ C, int M, int N, int K)
{
    __shared__ float As[16][APAD];   // As[k][m]
    __shared__ float Bs[16][APAD];   // Bs[k][n]

    const int tid = threadIdx.x;
    const int tr  = tid / 16;            // 0..15 -> rows tr*8..tr*8+7
    const int tc  = tid % 16;            // 0..15 -> cols tc*8..tc*8+7
    const int bm  = blockIdx.y * 128;
    const int bn  = blockIdx.x * 128;

    // A-tile load map: 512 float4 (128 rows x 16 cols); this thread does i, i+256
    const int ar0 = tid >> 2;                 // i/4 for i=tid
    const int ac0 = (tid & 3) << 2;
    // B-tile load map: 512 float4 (16 rows x 128 cols)
    const int br0 = tid >> 5;
    const int bc0 = (tid & 31) << 2;

    float acc[8][8];
#pragma unroll
    for (int i = 0; i < 8; i++)
#pragma unroll
        for (int j = 0; j < 8; j++) acc[i][j] = 0.0f;

    float4 pa0, pa1, pb0, pb1;

    // prefetch first tile
    pa0 = *(const float4*)(A + (size_t)(bm + ar0) * K + ac0);
    pa1 = *(const float4*)(A + (size_t)(bm + ar0 + 64) * K + ac0);
    pb0 = *(const float4*)(B + (size_t)br0 * N + bn + bc0);
    pb1 = *(const float4*)(B + (size_t)(br0 + 8) * N + bn + bc0);

    for (int k0 = 0; k0 < K; k0 += 16) {
        // store prefetched tile to smem
        As[ac0 + 0][ar0] = pa0.x; As[ac0 + 1][ar0] = pa0.y;
        As[ac0 + 2][ar0] = pa0.z; As[ac0 + 3][ar0] = pa0.w;
        As[ac0 + 0][ar0 + 64] = pa1.x; As[ac0 + 1][ar0 + 64] = pa1.y;
        As[ac0 + 2][ar0 + 64] = pa1.z; As[ac0 + 3][ar0 + 64] = pa1.w;
        *(float4*)&Bs[br0][bc0]     = pb0;
        *(float4*)&Bs[br0 + 8][bc0] = pb1;
        __syncthreads();

        // prefetch next tile
        if (k0 + 16 < K) {
            const float* Ap = A + k0 + 16;
            const float* Bp = B + (size_t)(k0 + 16) * N;
            pa0 = *(const float4*)(Ap + (size_t)(bm + ar0) * K + ac0);
            pa1 = *(const float4*)(Ap + (size_t)(bm + ar0 + 64) * K + ac0);
            pb0 = *(const float4*)(Bp + (size_t)br0 * N + bn + bc0);
            pb1 = *(const float4*)(Bp + (size_t)(br0 + 8) * N + bn + bc0);
        }

#pragma unroll
        for (int kk = 0; kk < 16; kk++) {
            float4 a0 = *(const float4*)&As[kk][tr * 8];
            float4 a1 = *(const float4*)&As[kk][tr * 8 + 4];
            float4 b0 = *(const float4*)&Bs[kk][tc * 8];
            float4 b1 = *(const float4*)&Bs[kk][tc * 8 + 4];
            float a[8] = {a0.x, a0.y, a0.z, a0.w, a1.x, a1.y, a1.z, a1.w};
            float b[8] = {b0.x, b0.y, b0.z, b0.w, b1.x, b1.y, b1.z, b1.w};
#pragma unroll
            for (int i = 0; i < 8; i++)
#pragma unroll
                for (int j = 0; j < 8; j++) acc[i][j] += a[i] * b[j];
        }
        __syncthreads();
    }

#pragma unroll
    for (int i = 0; i < 8; i++) {
        float* Cr = C + (size_t)(bm + tr * 8 + i) * N + bn + tc * 8;
        *(float4*)(Cr)     = make_float4(acc[i][0], acc[i][1], acc[i][2], acc[i][3]);
        *(float4*)(Cr + 4) = make_float4(acc[i][4], acc[i][5], acc[i][6], acc[i][7]);
    }
}

// ---------------------------------------------------------------------------
// RoPE in place, accurate trig (fast-math-proof). grid=(rows, nheads), 64 thr.
// ---------------------------------------------------------------------------
__global__ __launch_bounds__(64) void rope2(float* __restrict__ x, int nheads)
{
    const int pair = threadIdx.x;
    const int h    = blockIdx.y;
    const int row  = blockIdx.x;
    const int s    = row % SEQ;

    double inv_d = exp(-(double)pair * (1.0 / 64.0) * log(10000.0));
    float  inv_f = (float)inv_d;
    float  ang_f = (float)s * inv_f;

    float c  = (float)cos((double)ang_f);
    float sn = (float)sin((double)ang_f);

    float* p = x + (size_t)row * (nheads * HD) + h * HD + pair * 2;
    float x0 = p[0];
    float x1 = p[1];
    p[0] = x0 * c - x1 * sn;
    p[1] = x0 * sn + x1 * c;
}

// ---------------------------------------------------------------------------
// Causal GQA attention: one block per (query pos s, kv head g, batch b),
// computing all NREP=4 query heads that share this kv head.
// 128 threads. Probs kept as float4 (4 heads) in smem.
// ---------------------------------------------------------------------------
__global__ __launch_bounds__(128) void attn4(
    const float* __restrict__ Q, const float* __restrict__ K,
    const float* __restrict__ V, float* __restrict__ O)
{
    __shared__ float4 sp4[SEQ];       // probs[k] for 4 heads   (32 KB)
    __shared__ float4 qs4[HD];        // qs4[e] = {q_h0[e]..q_h3[e]} * scale
    __shared__ float  wredm[4][4];    // per-warp reduction scratch

    const int t    = threadIdx.x;     // 0..127
    const int lane = t & 31;
    const int warp = t >> 5;
    const int s    = blockIdx.x;
    const int g    = blockIdx.y;      // kv head
    const int b    = blockIdx.z;

    const float scale = 0.08838834764831845f;   // 1/sqrt(128)

    const float* Qb = Q + ((size_t)b * SEQ + s) * QSTR + (g * NREP) * HD;
    const float* Kb = K + (size_t)b * SEQ * KSTR + g * HD;
    const float* Vb = V + (size_t)b * SEQ * KSTR + g * HD;

    // interleave 4 query heads: qs4[e].{x,y,z,w} = head 0..3 at dim e
    {
        int e = t;   // HD == 128 == blockDim
        qs4[e] = make_float4(Qb[e] * scale, Qb[HD + e] * scale,
                             Qb[2 * HD + e] * scale, Qb[3 * HD + e] * scale);
    }
    __syncthreads();

    const int nk = s + 1;

    // ---- Pass 1: scores for 4 heads + local max ----
    float m0 = -INFINITY, m1 = -INFINITY, m2 = -INFINITY, m3 = -INFINITY;
    for (int k = t; k < nk; k += 128) {
        const float4* kr = (const float4*)(Kb + (size_t)k * KSTR);
        float d0 = 0.f, d1 = 0.f, d2 = 0.f, d3 = 0.f;
#pragma unroll
        for (int e4 = 0; e4 < 32; e4++) {
            float4 kv = kr[e4];
            float4 qa = qs4[e4 * 4 + 0];
            float4 qb = qs4[e4 * 4 + 1];
            float4 qc = qs4[e4 * 4 + 2];
            float4 qd = qs4[e4 * 4 + 3];
            d0 += qa.x * kv.x + qb.x * kv.y + qc.x * kv.z + qd.x * kv.w;
            d1 += qa.y * kv.x + qb.y * kv.y + qc.y * kv.z + qd.y * kv.w;
            d2 += qa.z * kv.x + qb.z * kv.y + qc.z * kv.z + qd.z * kv.w;
            d3 += qa.w * kv.x + qb.w * kv.y + qc.w * kv.z + qd.w * kv.w;
        }
        sp4[k] = make_float4(d0, d1, d2, d3);
        m0 = fmaxf(m0, d0); m1 = fmaxf(m1, d1);
        m2 = fmaxf(m2, d2); m3 = fmaxf(m3, d3);
    }
#pragma unroll
    for (int o = 16; o > 0; o >>= 1) {
        m0 = fmaxf(m0, __shfl_xor_sync(0xFFFFFFFFu, m0, o));
        m1 = fmaxf(m1, __shfl_xor_sync(0xFFFFFFFFu, m1, o));
        m2 = fmaxf(m2, __shfl_xor_sync(0xFFFFFFFFu, m2, o));
        m3 = fmaxf(m3, __shfl_xor_sync(0xFFFFFFFFu, m3, o));
    }
    if (lane == 0) {
        wredm[warp][0] = m0; wredm[warp][1] = m1;
        wredm[warp][2] = m2; wredm[warp][3] = m3;
    }
    __syncthreads();
    m0 = fmaxf(fmaxf(wredm[0][0], wredm[1][0]), fmaxf(wredm[2][0], wredm[3][0]));
    m1 = fmaxf(fmaxf(wredm[0][1], wredm[1][1]), fmaxf(wredm[2][1], wredm[3][1]));
    m2 = fmaxf(fmaxf(wredm[0][2], wredm[1][2]), fmaxf(wredm[2][2], wredm[3][2]));
    m3 = fmaxf(fmaxf(wredm[0][3], wredm[1][3]), fmaxf(wredm[2][3], wredm[3][3]));
    __syncthreads();   // protect wredm before reuse

    // ---- Pass 2: exp + local sum ----
    float l0 = 0.f, l1 = 0.f, l2 = 0.f, l3 = 0.f;
    for (int k = t; k < nk; k += 128) {
        float4 p = sp4[k];
        p.x = expf(p.x - m0); p.y = expf(p.y - m1);
        p.z = expf(p.z - m2); p.w = expf(p.w - m3);
        sp4[k] = p;
        l0 += p.x; l1 += p.y; l2 += p.z; l3 += p.w;
    }
#pragma unroll
    for (int o = 16; o > 0; o >>= 1) {
        l0 += __shfl_xor_sync(0xFFFFFFFFu, l0, o);
        l1 += __shfl_xor_sync(0xFFFFFFFFu, l1, o);
        l2 += __shfl_xor_sync(0xFFFFFFFFu, l2, o);
        l3 += __shfl_xor_sync(0xFFFFFFFFu, l3, o);
    }
    if (lane == 0) {
        wredm[warp][0] = l0; wredm[warp][1] = l1;
        wredm[warp][2] = l2; wredm[warp][3] = l3;
    }
    __syncthreads();
    l0 = wredm[0][0] + wredm[1][0] + wredm[2][0] + wredm[3][0];
    l1 = wredm[0][1] + wredm[1][1] + wredm[2][1] + wredm[3][1];
    l2 = wredm[0][2] + wredm[1][2] + wredm[2][2] + wredm[3][2];
    l3 = wredm[0][3] + wredm[1][3] + wredm[2][3] + wredm[3][3];
    // (the __syncthreads above also makes all sp4 writes visible)

    // ---- PV: thread t owns value dim t for all 4 heads ----
    float a0 = 0.f, a1 = 0.f, a2 = 0.f, a3 = 0.f;
    const float* Vt = Vb + t;
    int k = 0;
    for (; k + 4 <= nk; k += 4) {
#pragma unroll
        for (int u = 0; u < 4; u++) {
            float v  = Vt[(size_t)(k + u) * KSTR];
            float4 p = sp4[k + u];
            a0 += p.x * v; a1 += p.y * v; a2 += p.z * v; a3 += p.w * v;
        }
    }
    for (; k < nk; k++) {
        float v  = Vt[(size_t)k * KSTR];
        float4 p = sp4[k];
        a0 += p.x * v; a1 += p.y * v; a2 += p.z * v; a3 += p.w * v;
    }

    float* Ob = O + ((size_t)b * SEQ + s) * QSTR + (g * NREP) * HD + t;
    Ob[0]      = a0 / l0;
    Ob[HD]     = a1 / l1;
    Ob[2 * HD] = a2 / l2;
    Ob[3 * HD] = a3 / l3;
}

// ---------------------------------------------------------------------------
extern "C" void kernel_launch(void* const* d_in, const int* in_sizes, int n_in,
                              void* d_out, int out_size)
{
    const float *x, *wq, *wk, *wv, *wo;
    if (n_in >= 7 && in_sizes[0] == 1 && in_sizes[1] == 1) {
        if (in_sizes[2] == 16777216) {
            x  = (const float*)d_in[2];
            wq = (const float*)d_in[3];
            wk = (const float*)d_in[4];
            wv = (const float*)d_in[5];
            wo = (const float*)d_in[6];
        } else {
            wk = (const float*)d_in[2];
            wo = (const float*)d_in[3];
            wq = (const float*)d_in[4];
            wv = (const float*)d_in[5];
            x  = (const float*)d_in[6];
        }
    } else {
        x  = (const float*)d_in[0];
        wq = (const float*)d_in[1];
        wk = (const float*)d_in[2];
        wv = (const float*)d_in[3];
        wo = (const float*)d_in[4];
    }
    float* out = (float*)d_out;

    float* Qp; cudaGetSymbolAddress((void**)&Qp, g_Q);
    float* Kp; cudaGetSymbolAddress((void**)&Kp, g_K);
    float* Vp; cudaGetSymbolAddress((void**)&Vp, g_V);
    float* Op; cudaGetSymbolAddress((void**)&Op, g_O);

    const int M = BSZ * SEQ;   // 4096

    // QKV projections
    gemm128<<<dim3(DMODEL / 128, M / 128), 256>>>(x, wq, Qp, M, DMODEL, DMODEL);
    gemm128<<<dim3(KSTR / 128, M / 128), 256>>>(x, wk, Kp, M, KSTR, DMODEL);
    gemm128<<<dim3(KSTR / 128, M / 128), 256>>>(x, wv, Vp, M, KSTR, DMODEL);

    // RoPE (in place on Q and K)
    rope2<<<dim3(M, NH), 64>>>(Qp, NH);
    rope2<<<dim3(M, NKV), 64>>>(Kp, NKV);

    // Causal GQA attention (4 q-heads per block)
    attn4<<<dim3(SEQ, NKV, BSZ), 128>>>(Qp, Kp, Vp, Op);

    // Output projection
    gemm128<<<dim3(DMODEL / 128, M / 128), 256>>>(Op, wo, out, M, DMODEL, DMODEL);
}

// round 6
// speedup vs baseline: 5.7548x; 1.3762x over previous
#include <cuda_runtime.h>
#include <cuda_bf16.h>
#include <math.h>

#define BSZ 2
#define SEQ 2048
#define DMODEL 4096
#define NH 32
#define NKV 8
#define NREP 4
#define HD 128

#define QSTR (NH * HD)
#define KSTR (NKV * HD)
#define MROWS (BSZ * SEQ)

// ---- fp32 scratch ----
__device__ float g_Q[MROWS * QSTR];
__device__ float g_K[MROWS * KSTR];
__device__ float g_V[MROWS * KSTR];
__device__ float g_O[MROWS * QSTR];

// ---- bf16 split buffers ----
__device__ __nv_bfloat16 g_x_hi[MROWS * DMODEL];
__device__ __nv_bfloat16 g_x_lo[MROWS * DMODEL];
__device__ __nv_bfloat16 g_wq_hi[DMODEL * DMODEL];
__device__ __nv_bfloat16 g_wq_lo[DMODEL * DMODEL];
__device__ __nv_bfloat16 g_wk_hi[DMODEL * KSTR];
__device__ __nv_bfloat16 g_wk_lo[DMODEL * KSTR];
__device__ __nv_bfloat16 g_wv_hi[DMODEL * KSTR];
__device__ __nv_bfloat16 g_wv_lo[DMODEL * KSTR];
__device__ __nv_bfloat16 g_wo_hi[DMODEL * DMODEL];
__device__ __nv_bfloat16 g_wo_lo[DMODEL * DMODEL];
__device__ __nv_bfloat16 g_o_hi[MROWS * DMODEL];
__device__ __nv_bfloat16 g_o_lo[MROWS * DMODEL];

// ---------------------------------------------------------------------------
// asm helpers
// ---------------------------------------------------------------------------
__device__ __forceinline__ void cp16(unsigned int dst, const void* src)
{
    asm volatile("cp.async.cg.shared.global [%0], [%1], 16;" :: "r"(dst), "l"(src));
}
__device__ __forceinline__ void cp_commit()
{
    asm volatile("cp.async.commit_group;");
}
__device__ __forceinline__ void cp_wait1()
{
    asm volatile("cp.async.wait_group 1;");
}
__device__ __forceinline__ void cp_wait0()
{
    asm volatile("cp.async.wait_group 0;");
}
__device__ __forceinline__ void ldm_x4(unsigned int* r, unsigned int addr)
{
    asm volatile("ldmatrix.sync.aligned.m8n8.x4.shared.b16 {%0,%1,%2,%3}, [%4];"
                 : "=r"(r[0]), "=r"(r[1]), "=r"(r[2]), "=r"(r[3]) : "r"(addr));
}
__device__ __forceinline__ void ldm_x4t(unsigned int* r, unsigned int addr)
{
    asm volatile("ldmatrix.sync.aligned.m8n8.x4.trans.shared.b16 {%0,%1,%2,%3}, [%4];"
                 : "=r"(r[0]), "=r"(r[1]), "=r"(r[2]), "=r"(r[3]) : "r"(addr));
}
__device__ __forceinline__ void mma16816(float* d, const unsigned int* a,
                                         unsigned int b0, unsigned int b1)
{
    asm volatile(
        "mma.sync.aligned.m16n8k16.row.col.f32.bf16.bf16.f32 "
        "{%0,%1,%2,%3}, {%4,%5,%6,%7}, {%8,%9}, {%0,%1,%2,%3};"
        : "+f"(d[0]), "+f"(d[1]), "+f"(d[2]), "+f"(d[3])
        : "r"(a[0]), "r"(a[1]), "r"(a[2]), "r"(a[3]), "r"(b0), "r"(b1));
}

// ---------------------------------------------------------------------------
// fp32 -> (hi, lo) bf16 split. n % 4 == 0.
// ---------------------------------------------------------------------------
__global__ __launch_bounds__(256) void cvt_split(
    const float* __restrict__ in, __nv_bfloat16* __restrict__ hi,
    __nv_bfloat16* __restrict__ lo, int n)
{
    int i = (blockIdx.x * blockDim.x + threadIdx.x) * 4;
    if (i >= n) {
        return;
    }
    float4 v = *(const float4*)(in + i);
    float vv[4];
    vv[0] = v.x; vv[1] = v.y; vv[2] = v.z; vv[3] = v.w;
    unsigned short H[4];
    unsigned short L[4];
#pragma unroll
    for (int c = 0; c < 4; c++) {
        __nv_bfloat16 h = __float2bfloat16(vv[c]);
        __nv_bfloat16 l = __float2bfloat16(vv[c] - __bfloat162float(h));
        H[c] = *(unsigned short*)&h;
        L[c] = *(unsigned short*)&l;
    }
    *(ushort4*)(hi + i) = make_ushort4(H[0], H[1], H[2], H[3]);
    *(ushort4*)(lo + i) = make_ushort4(L[0], L[1], L[2], L[3]);
}

// ---------------------------------------------------------------------------
// Tensor-core GEMM, bf16 3-term split (fp32 accum).
// A row-major [M,K], B row-major [K,N]. M%128==0, N%128==0, K%32==0.
// 128x128 tile, BK=32, 256 threads (2x4 warps, 64x32 each), cp.async 2-stage.
// ---------------------------------------------------------------------------
#define AST 40
#define BST 136
#define AS_BYTES (128 * AST * 2)
#define BS_BYTES (32 * BST * 2)
#define STAGE_BYTES (2 * AS_BYTES + 2 * BS_BYTES)
#define GEMM_SMEM (2 * STAGE_BYTES)

__device__ __forceinline__ void issue_stage(
    unsigned int s0,
    const __nv_bfloat16* __restrict__ Ahi, const __nv_bfloat16* __restrict__ Alo,
    const __nv_bfloat16* __restrict__ Bhi, const __nv_bfloat16* __restrict__ Blo,
    int K, int N, int bm, int bn, int k0,
    int ar0, int ar1, int ak, int br0, int br1, int bc)
{
    unsigned int da0 = s0 + (unsigned int)(ar0 * AST + ak) * 2u;
    cp16(da0, Ahi + (size_t)(bm + ar0) * K + k0 + ak);
    cp16(da0 + AS_BYTES, Alo + (size_t)(bm + ar0) * K + k0 + ak);
    unsigned int da1 = s0 + (unsigned int)(ar1 * AST + ak) * 2u;
    cp16(da1, Ahi + (size_t)(bm + ar1) * K + k0 + ak);
    cp16(da1 + AS_BYTES, Alo + (size_t)(bm + ar1) * K + k0 + ak);
    unsigned int db0 = s0 + 2u * AS_BYTES + (unsigned int)(br0 * BST + bc) * 2u;
    cp16(db0, Bhi + (size_t)(k0 + br0) * N + bn + bc);
    cp16(db0 + BS_BYTES, Blo + (size_t)(k0 + br0) * N + bn + bc);
    unsigned int db1 = s0 + 2u * AS_BYTES + (unsigned int)(br1 * BST + bc) * 2u;
    cp16(db1, Bhi + (size_t)(k0 + br1) * N + bn + bc);
    cp16(db1 + BS_BYTES, Blo + (size_t)(k0 + br1) * N + bn + bc);
}

__global__ __launch_bounds__(256) void gemm_bf16x3(
    const __nv_bfloat16* __restrict__ Ahi, const __nv_bfloat16* __restrict__ Alo,
    const __nv_bfloat16* __restrict__ Bhi, const __nv_bfloat16* __restrict__ Blo,
    float* __restrict__ C, int M, int N, int K)
{
    extern __shared__ char smraw[];
    const int tid  = threadIdx.x;
    const int warp = tid >> 5;
    const int lane = tid & 31;
    const int wm   = warp >> 2;
    const int wn   = warp & 3;
    const int bm   = blockIdx.y * 128;
    const int bn   = blockIdx.x * 128;

    unsigned int sbase = (unsigned int)__cvta_generic_to_shared(smraw);

    float acc[4][4][4];
#pragma unroll
    for (int i = 0; i < 4; i++) {
#pragma unroll
        for (int j = 0; j < 4; j++) {
#pragma unroll
            for (int r = 0; r < 4; r++) {
                acc[i][j][r] = 0.0f;
            }
        }
    }

    const int ar0 = tid >> 2;
    const int ar1 = (tid + 256) >> 2;
    const int ak  = (tid & 3) << 3;
    const int br0 = tid >> 4;
    const int br1 = (tid + 256) >> 4;
    const int bc  = (tid & 15) << 3;

    const int niter = K / 32;
    issue_stage(sbase, Ahi, Alo, Bhi, Blo, K, N, bm, bn, 0,
                ar0, ar1, ak, br0, br1, bc);
    cp_commit();

    const int arow  = lane & 15;
    const int acolh = (lane >> 4) << 3;

    for (int it = 0; it < niter; it++) {
        int cur = it & 1;
        if (it + 1 < niter) {
            issue_stage(sbase + (unsigned int)(cur ^ 1) * STAGE_BYTES,
                        Ahi, Alo, Bhi, Blo, K, N, bm, bn, (it + 1) * 32,
                        ar0, ar1, ak, br0, br1, bc);
            cp_commit();
            cp_wait1();
        } else {
            cp_wait0();
        }
        __syncthreads();

        unsigned int s0   = sbase + (unsigned int)cur * STAGE_BYTES;
        unsigned int sBhi = s0 + 2u * AS_BYTES;

#pragma unroll
        for (int ks = 0; ks < 2; ks++) {
            int k16 = ks * 16;
            unsigned int a_hi[4][4];
            unsigned int a_lo[4][4];
#pragma unroll
            for (int mi = 0; mi < 4; mi++) {
                unsigned int addr = s0 +
                    (unsigned int)((wm * 64 + mi * 16 + arow) * AST + k16 + acolh) * 2u;
                ldm_x4(a_hi[mi], addr);
                ldm_x4(a_lo[mi], addr + AS_BYTES);
            }
            unsigned int b_hi[2][4];
            unsigned int b_lo[2][4];
#pragma unroll
            for (int nj = 0; nj < 2; nj++) {
                unsigned int addr = sBhi +
                    (unsigned int)((k16 + arow) * BST + wn * 32 + nj * 16 + acolh) * 2u;
                ldm_x4t(b_hi[nj], addr);
                ldm_x4t(b_lo[nj], addr + BS_BYTES);
            }
#pragma unroll
            for (int mi = 0; mi < 4; mi++) {
#pragma unroll
                for (int nj = 0; nj < 2; nj++) {
                    mma16816(acc[mi][2 * nj],     a_hi[mi], b_hi[nj][0], b_hi[nj][1]);
                    mma16816(acc[mi][2 * nj + 1], a_hi[mi], b_hi[nj][2], b_hi[nj][3]);
                    mma16816(acc[mi][2 * nj],     a_hi[mi], b_lo[nj][0], b_lo[nj][1]);
                    mma16816(acc[mi][2 * nj + 1], a_hi[mi], b_lo[nj][2], b_lo[nj][3]);
                    mma16816(acc[mi][2 * nj],     a_lo[mi], b_hi[nj][0], b_hi[nj][1]);
                    mma16816(acc[mi][2 * nj + 1], a_lo[mi], b_hi[nj][2], b_hi[nj][3]);
                }
            }
        }
        __syncthreads();
    }

    const int r0 = bm + wm * 64;
    const int c0 = bn + wn * 32;
#pragma unroll
    for (int mi = 0; mi < 4; mi++) {
#pragma unroll
        for (int ng = 0; ng < 4; ng++) {
            int row = r0 + mi * 16 + (lane >> 2);
            int col = c0 + ng * 8 + (lane & 3) * 2;
            *(float2*)(C + (size_t)row * N + col) =
                make_float2(acc[mi][ng][0], acc[mi][ng][1]);
            *(float2*)(C + (size_t)(row + 8) * N + col) =
                make_float2(acc[mi][ng][2], acc[mi][ng][3]);
        }
    }
}

// ---------------------------------------------------------------------------
// RoPE in place, accurate trig (fast-math-proof). grid=(rows, nheads), 64 thr.
// ---------------------------------------------------------------------------
__global__ __launch_bounds__(64) void rope2(float* __restrict__ x, int nheads)
{
    const int pair = threadIdx.x;
    const int h    = blockIdx.y;
    const int row  = blockIdx.x;
    const int s    = row % SEQ;

    double inv_d = exp(-(double)pair * (1.0 / 64.0) * log(10000.0));
    float  inv_f = (float)inv_d;
    float  ang_f = (float)s * inv_f;

    float c  = (float)cos((double)ang_f);
    float sn = (float)sin((double)ang_f);

    float* p = x + (size_t)row * (nheads * HD) + h * HD + pair * 2;
    float x0 = p[0];
    float x1 = p[1];
    p[0] = x0 * c - x1 * sn;
    p[1] = x0 * sn + x1 * c;
}

// ---------------------------------------------------------------------------
// Causal GQA attention: one block per (s, kv head g, b); NREP=4 q heads.
// ---------------------------------------------------------------------------
__global__ __launch_bounds__(128) void attn4(
    const float* __restrict__ Q, const float* __restrict__ K,
    const float* __restrict__ V, float* __restrict__ O)
{
    __shared__ float4 sp4[SEQ];
    __shared__ float4 qs4[HD];
    __shared__ float  wredm[4][4];

    const int t    = threadIdx.x;
    const int lane = t & 31;
    const int warp = t >> 5;
    const int s    = blockIdx.x;
    const int g    = blockIdx.y;
    const int b    = blockIdx.z;

    const float scale = 0.08838834764831845f;

    const float* Qb = Q + ((size_t)b * SEQ + s) * QSTR + (g * NREP) * HD;
    const float* Kb = K + (size_t)b * SEQ * KSTR + g * HD;
    const float* Vb = V + (size_t)b * SEQ * KSTR + g * HD;

    qs4[t] = make_float4(Qb[t] * scale, Qb[HD + t] * scale,
                         Qb[2 * HD + t] * scale, Qb[3 * HD + t] * scale);
    __syncthreads();

    const int nk = s + 1;

    float m0 = -INFINITY;
    float m1 = -INFINITY;
    float m2 = -INFINITY;
    float m3 = -INFINITY;
    for (int k = t; k < nk; k += 128) {
        const float4* kr = (const float4*)(Kb + (size_t)k * KSTR);
        float d0 = 0.f, d1 = 0.f, d2 = 0.f, d3 = 0.f;
#pragma unroll
        for (int e4 = 0; e4 < 32; e4++) {
            float4 kv = kr[e4];
            float4 qa = qs4[e4 * 4 + 0];
            float4 qb = qs4[e4 * 4 + 1];
            float4 qc = qs4[e4 * 4 + 2];
            float4 qd = qs4[e4 * 4 + 3];
            d0 += qa.x * kv.x + qb.x * kv.y + qc.x * kv.z + qd.x * kv.w;
            d1 += qa.y * kv.x + qb.y * kv.y + qc.y * kv.z + qd.y * kv.w;
            d2 += qa.z * kv.x + qb.z * kv.y + qc.z * kv.z + qd.z * kv.w;
            d3 += qa.w * kv.x + qb.w * kv.y + qc.w * kv.z + qd.w * kv.w;
        }
        sp4[k] = make_float4(d0, d1, d2, d3);
        m0 = fmaxf(m0, d0);
        m1 = fmaxf(m1, d1);
        m2 = fmaxf(m2, d2);
        m3 = fmaxf(m3, d3);
    }
#pragma unroll
    for (int o = 16; o > 0; o >>= 1) {
        m0 = fmaxf(m0, __shfl_xor_sync(0xFFFFFFFFu, m0, o));
        m1 = fmaxf(m1, __shfl_xor_sync(0xFFFFFFFFu, m1, o));
        m2 = fmaxf(m2, __shfl_xor_sync(0xFFFFFFFFu, m2, o));
        m3 = fmaxf(m3, __shfl_xor_sync(0xFFFFFFFFu, m3, o));
    }
    if (lane == 0) {
        wredm[warp][0] = m0;
        wredm[warp][1] = m1;
        wredm[warp][2] = m2;
        wredm[warp][3] = m3;
    }
    __syncthreads();
    m0 = fmaxf(fmaxf(wredm[0][0], wredm[1][0]), fmaxf(wredm[2][0], wredm[3][0]));
    m1 = fmaxf(fmaxf(wredm[0][1], wredm[1][1]), fmaxf(wredm[2][1], wredm[3][1]));
    m2 = fmaxf(fmaxf(wredm[0][2], wredm[1][2]), fmaxf(wredm[2][2], wredm[3][2]));
    m3 = fmaxf(fmaxf(wredm[0][3], wredm[1][3]), fmaxf(wredm[2][3], wredm[3][3]));
    __syncthreads();

    float l0 = 0.f, l1 = 0.f, l2 = 0.f, l3 = 0.f;
    for (int k = t; k < nk; k += 128) {
        float4 p = sp4[k];
        p.x = expf(p.x - m0);
        p.y = expf(p.y - m1);
        p.z = expf(p.z - m2);
        p.w = expf(p.w - m3);
        sp4[k] = p;
        l0 += p.x;
        l1 += p.y;
        l2 += p.z;
        l3 += p.w;
    }
#pragma unroll
    for (int o = 16; o > 0; o >>= 1) {
        l0 += __shfl_xor_sync(0xFFFFFFFFu, l0, o);
        l1 += __shfl_xor_sync(0xFFFFFFFFu, l1, o);
        l2 += __shfl_xor_sync(0xFFFFFFFFu, l2, o);
        l3 += __shfl_xor_sync(0xFFFFFFFFu, l3, o);
    }
    if (lane == 0) {
        wredm[warp][0] = l0;
        wredm[warp][1] = l1;
        wredm[warp][2] = l2;
        wredm[warp][3] = l3;
    }
    __syncthreads();
    l0 = wredm[0][0] + wredm[1][0] + wredm[2][0] + wredm[3][0];
    l1 = wredm[0][1] + wredm[1][1] + wredm[2][1] + wredm[3][1];
    l2 = wredm[0][2] + wredm[1][2] + wredm[2][2] + wredm[3][2];
    l3 = wredm[0][3] + wredm[1][3] + wredm[2][3] + wredm[3][3];

    float a0 = 0.f, a1 = 0.f, a2 = 0.f, a3 = 0.f;
    const float* Vt = Vb + t;
    int k = 0;
    for (; k + 4 <= nk; k += 4) {
#pragma unroll
        for (int u = 0; u < 4; u++) {
            float v  = Vt[(size_t)(k + u) * KSTR];
            float4 p = sp4[k + u];
            a0 += p.x * v;
            a1 += p.y * v;
            a2 += p.z * v;
            a3 += p.w * v;
        }
    }
    for (; k < nk; k++) {
        float v  = Vt[(size_t)k * KSTR];
        float4 p = sp4[k];
        a0 += p.x * v;
        a1 += p.y * v;
        a2 += p.z * v;
        a3 += p.w * v;
    }

    float* Ob = O + ((size_t)b * SEQ + s) * QSTR + (g * NREP) * HD + t;
    Ob[0]      = a0 / l0;
    Ob[HD]     = a1 / l1;
    Ob[2 * HD] = a2 / l2;
    Ob[3 * HD] = a3 / l3;
}

// ---------------------------------------------------------------------------
extern "C" void kernel_launch(void* const* d_in, const int* in_sizes, int n_in,
                              void* d_out, int out_size)
{
    const float* x;
    const float* wq;
    const float* wk;
    const float* wv;
    const float* wo;
    if (n_in >= 7 && in_sizes[0] == 1 && in_sizes[1] == 1) {
        if (in_sizes[2] == 16777216) {
            x  = (const float*)d_in[2];
            wq = (const float*)d_in[3];
            wk = (const float*)d_in[4];
            wv = (const float*)d_in[5];
            wo = (const float*)d_in[6];
        } else {
            wk = (const float*)d_in[2];
            wo = (const float*)d_in[3];
            wq = (const float*)d_in[4];
            wv = (const float*)d_in[5];
            x  = (const float*)d_in[6];
        }
    } else {
        x  = (const float*)d_in[0];
        wq = (const float*)d_in[1];
        wk = (const float*)d_in[2];
        wv = (const float*)d_in[3];
        wo = (const float*)d_in[4];
    }
    float* out = (float*)d_out;

    float* Qp;
    float* Kp;
    float* Vp;
    float* Op;
    cudaGetSymbolAddress((void**)&Qp, g_Q);
    cudaGetSymbolAddress((void**)&Kp, g_K);
    cudaGetSymbolAddress((void**)&Vp, g_V);
    cudaGetSymbolAddress((void**)&Op, g_O);

    __nv_bfloat16* xh;
    __nv_bfloat16* xl;
    __nv_bfloat16* qh;
    __nv_bfloat16* ql;
    __nv_bfloat16* kh;
    __nv_bfloat16* kl;
    __nv_bfloat16* vh;
    __nv_bfloat16* vl;
    __nv_bfloat16* oh;
    __nv_bfloat16* ol;
    __nv_bfloat16* ph;
    __nv_bfloat16* pl;
    cudaGetSymbolAddress((void**)&xh, g_x_hi);
    cudaGetSymbolAddress((void**)&xl, g_x_lo);
    cudaGetSymbolAddress((void**)&qh, g_wq_hi);
    cudaGetSymbolAddress((void**)&ql, g_wq_lo);
    cudaGetSymbolAddress((void**)&kh, g_wk_hi);
    cudaGetSymbolAddress((void**)&kl, g_wk_lo);
    cudaGetSymbolAddress((void**)&vh, g_wv_hi);
    cudaGetSymbolAddress((void**)&vl, g_wv_lo);
    cudaGetSymbolAddress((void**)&oh, g_wo_hi);
    cudaGetSymbolAddress((void**)&ol, g_wo_lo);
    cudaGetSymbolAddress((void**)&ph, g_o_hi);
    cudaGetSymbolAddress((void**)&pl, g_o_lo);

    const int M = MROWS;

    const int n1 = M * DMODEL;
    const int n2 = DMODEL * DMODEL;
    const int n3 = DMODEL * KSTR;
    cvt_split<<<n1 / 1024, 256>>>(x,  xh, xl, n1);
    cvt_split<<<n2 / 1024, 256>>>(wq, qh, ql, n2);
    cvt_split<<<n3 / 1024, 256>>>(wk, kh, kl, n3);
    cvt_split<<<n3 / 1024, 256>>>(wv, vh, vl, n3);
    cvt_split<<<n2 / 1024, 256>>>(wo, oh, ol, n2);

    cudaFuncSetAttribute(gemm_bf16x3,
                         cudaFuncAttributeMaxDynamicSharedMemorySize, GEMM_SMEM);

    gemm_bf16x3<<<dim3(DMODEL / 128, M / 128), 256, GEMM_SMEM>>>(
        xh, xl, qh, ql, Qp, M, DMODEL, DMODEL);
    gemm_bf16x3<<<dim3(KSTR / 128, M / 128), 256, GEMM_SMEM>>>(
        xh, xl, kh, kl, Kp, M, KSTR, DMODEL);
    gemm_bf16x3<<<dim3(KSTR / 128, M / 128), 256, GEMM_SMEM>>>(
        xh, xl, vh, vl, Vp, M, KSTR, DMODEL);

    rope2<<<dim3(M, NH), 64>>>(Qp, NH);
    rope2<<<dim3(M, NKV), 64>>>(Kp, NKV);

    attn4<<<dim3(SEQ, NKV, BSZ), 128>>>(Qp, Kp, Vp, Op);

    cvt_split<<<(M * DMODEL) / 1024, 256>>>(Op, ph, pl, M * DMODEL);
    gemm_bf16x3<<<dim3(DMODEL / 128, M / 128), 256, GEMM_SMEM>>>(
        ph, pl, oh, ol, out, M, DMODEL, DMODEL);
}

// round 7
// speedup vs baseline: 13.9654x; 2.4267x over previous
#include <cuda_runtime.h>
#include <cuda_bf16.h>
#include <math.h>

#define BSZ 2
#define SEQ 2048
#define DMODEL 4096
#define NH 32
#define NKV 8
#define NREP 4
#define HD 128

#define QSTR (NH * HD)
#define KSTR (NKV * HD)
#define MROWS (BSZ * SEQ)

// ---- fp32 scratch ----
__device__ float g_Q[MROWS * QSTR];
__device__ float g_K[MROWS * KSTR];
__device__ float g_V[MROWS * KSTR];
__device__ float g_O[MROWS * QSTR];

// ---- bf16 split buffers (GEMM inputs) ----
__device__ __nv_bfloat16 g_x_hi[MROWS * DMODEL];
__device__ __nv_bfloat16 g_x_lo[MROWS * DMODEL];
__device__ __nv_bfloat16 g_wq_hi[DMODEL * DMODEL];
__device__ __nv_bfloat16 g_wq_lo[DMODEL * DMODEL];
__device__ __nv_bfloat16 g_wk_hi[DMODEL * KSTR];
__device__ __nv_bfloat16 g_wk_lo[DMODEL * KSTR];
__device__ __nv_bfloat16 g_wv_hi[DMODEL * KSTR];
__device__ __nv_bfloat16 g_wv_lo[DMODEL * KSTR];
__device__ __nv_bfloat16 g_wo_hi[DMODEL * DMODEL];
__device__ __nv_bfloat16 g_wo_lo[DMODEL * DMODEL];
__device__ __nv_bfloat16 g_o_hi[MROWS * DMODEL];
__device__ __nv_bfloat16 g_o_lo[MROWS * DMODEL];

// ---- bf16 split buffers (attention inputs, post-RoPE) ----
__device__ __nv_bfloat16 g_qb_hi[MROWS * QSTR];
__device__ __nv_bfloat16 g_qb_lo[MROWS * QSTR];
__device__ __nv_bfloat16 g_kb_hi[MROWS * KSTR];
__device__ __nv_bfloat16 g_kb_lo[MROWS * KSTR];
__device__ __nv_bfloat16 g_vb_hi[MROWS * KSTR];
__device__ __nv_bfloat16 g_vb_lo[MROWS * KSTR];

// ---------------------------------------------------------------------------
// asm helpers
// ---------------------------------------------------------------------------
__device__ __forceinline__ void cp16(unsigned int dst, const void* src)
{
    asm volatile("cp.async.cg.shared.global [%0], [%1], 16;" :: "r"(dst), "l"(src));
}
__device__ __forceinline__ void cp_commit()
{
    asm volatile("cp.async.commit_group;");
}
__device__ __forceinline__ void cp_wait1()
{
    asm volatile("cp.async.wait_group 1;");
}
__device__ __forceinline__ void cp_wait0()
{
    asm volatile("cp.async.wait_group 0;");
}
__device__ __forceinline__ void ldm_x4(unsigned int* r, unsigned int addr)
{
    asm volatile("ldmatrix.sync.aligned.m8n8.x4.shared.b16 {%0,%1,%2,%3}, [%4];"
                 : "=r"(r[0]), "=r"(r[1]), "=r"(r[2]), "=r"(r[3]) : "r"(addr));
}
__device__ __forceinline__ void ldm_x4t(unsigned int* r, unsigned int addr)
{
    asm volatile("ldmatrix.sync.aligned.m8n8.x4.trans.shared.b16 {%0,%1,%2,%3}, [%4];"
                 : "=r"(r[0]), "=r"(r[1]), "=r"(r[2]), "=r"(r[3]) : "r"(addr));
}
__device__ __forceinline__ void mma16816(float* d, const unsigned int* a,
                                         unsigned int b0, unsigned int b1)
{
    asm volatile(
        "mma.sync.aligned.m16n8k16.row.col.f32.bf16.bf16.f32 "
        "{%0,%1,%2,%3}, {%4,%5,%6,%7}, {%8,%9}, {%0,%1,%2,%3};"
        : "+f"(d[0]), "+f"(d[1]), "+f"(d[2]), "+f"(d[3])
        : "r"(a[0]), "r"(a[1]), "r"(a[2]), "r"(a[3]), "r"(b0), "r"(b1));
}
__device__ __forceinline__ unsigned int pack_bf2(float x, float y)
{
    __nv_bfloat162 t = __floats2bfloat162_rn(x, y);
    return *(unsigned int*)&t;
}

// ---------------------------------------------------------------------------
// fp32 -> (hi, lo) bf16 split. n % 4 == 0.
// ---------------------------------------------------------------------------
__global__ __launch_bounds__(256) void cvt_split(
    const float* __restrict__ in, __nv_bfloat16* __restrict__ hi,
    __nv_bfloat16* __restrict__ lo, int n)
{
    int i = (blockIdx.x * blockDim.x + threadIdx.x) * 4;
    if (i >= n) {
        return;
    }
    float4 v = *(const float4*)(in + i);
    float vv[4];
    vv[0] = v.x; vv[1] = v.y; vv[2] = v.z; vv[3] = v.w;
    unsigned short H[4];
    unsigned short L[4];
#pragma unroll
    for (int c = 0; c < 4; c++) {
        __nv_bfloat16 h = __float2bfloat16(vv[c]);
        __nv_bfloat16 l = __float2bfloat16(vv[c] - __bfloat162float(h));
        H[c] = *(unsigned short*)&h;
        L[c] = *(unsigned short*)&l;
    }
    *(ushort4*)(hi + i) = make_ushort4(H[0], H[1], H[2], H[3]);
    *(ushort4*)(lo + i) = make_ushort4(L[0], L[1], L[2], L[3]);
}

// ---------------------------------------------------------------------------
// Tensor-core GEMM, bf16 3-term split (fp32 accum). (unchanged from R6)
// ---------------------------------------------------------------------------
#define AST 40
#define BST 136
#define AS_BYTES (128 * AST * 2)
#define BS_BYTES (32 * BST * 2)
#define STAGE_BYTES (2 * AS_BYTES + 2 * BS_BYTES)
#define GEMM_SMEM (2 * STAGE_BYTES)

__device__ __forceinline__ void issue_stage(
    unsigned int s0,
    const __nv_bfloat16* __restrict__ Ahi, const __nv_bfloat16* __restrict__ Alo,
    const __nv_bfloat16* __restrict__ Bhi, const __nv_bfloat16* __restrict__ Blo,
    int K, int N, int bm, int bn, int k0,
    int ar0, int ar1, int ak, int br0, int br1, int bc)
{
    unsigned int da0 = s0 + (unsigned int)(ar0 * AST + ak) * 2u;
    cp16(da0, Ahi + (size_t)(bm + ar0) * K + k0 + ak);
    cp16(da0 + AS_BYTES, Alo + (size_t)(bm + ar0) * K + k0 + ak);
    unsigned int da1 = s0 + (unsigned int)(ar1 * AST + ak) * 2u;
    cp16(da1, Ahi + (size_t)(bm + ar1) * K + k0 + ak);
    cp16(da1 + AS_BYTES, Alo + (size_t)(bm + ar1) * K + k0 + ak);
    unsigned int db0 = s0 + 2u * AS_BYTES + (unsigned int)(br0 * BST + bc) * 2u;
    cp16(db0, Bhi + (size_t)(k0 + br0) * N + bn + bc);
    cp16(db0 + BS_BYTES, Blo + (size_t)(k0 + br0) * N + bn + bc);
    unsigned int db1 = s0 + 2u * AS_BYTES + (unsigned int)(br1 * BST + bc) * 2u;
    cp16(db1, Bhi + (size_t)(k0 + br1) * N + bn + bc);
    cp16(db1 + BS_BYTES, Blo + (size_t)(k0 + br1) * N + bn + bc);
}

__global__ __launch_bounds__(256) void gemm_bf16x3(
    const __nv_bfloat16* __restrict__ Ahi, const __nv_bfloat16* __restrict__ Alo,
    const __nv_bfloat16* __restrict__ Bhi, const __nv_bfloat16* __restrict__ Blo,
    float* __restrict__ C, int M, int N, int K)
{
    extern __shared__ char smraw[];
    const int tid  = threadIdx.x;
    const int warp = tid >> 5;
    const int lane = tid & 31;
    const int wm   = warp >> 2;
    const int wn   = warp & 3;
    const int bm   = blockIdx.y * 128;
    const int bn   = blockIdx.x * 128;

    unsigned int sbase = (unsigned int)__cvta_generic_to_shared(smraw);

    float acc[4][4][4];
#pragma unroll
    for (int i = 0; i < 4; i++) {
#pragma unroll
        for (int j = 0; j < 4; j++) {
#pragma unroll
            for (int r = 0; r < 4; r++) {
                acc[i][j][r] = 0.0f;
            }
        }
    }

    const int ar0 = tid >> 2;
    const int ar1 = (tid + 256) >> 2;
    const int ak  = (tid & 3) << 3;
    const int br0 = tid >> 4;
    const int br1 = (tid + 256) >> 4;
    const int bc  = (tid & 15) << 3;

    const int niter = K / 32;
    issue_stage(sbase, Ahi, Alo, Bhi, Blo, K, N, bm, bn, 0,
                ar0, ar1, ak, br0, br1, bc);
    cp_commit();

    const int arow  = lane & 15;
    const int acolh = (lane >> 4) << 3;

    for (int it = 0; it < niter; it++) {
        int cur = it & 1;
        if (it + 1 < niter) {
            issue_stage(sbase + (unsigned int)(cur ^ 1) * STAGE_BYTES,
                        Ahi, Alo, Bhi, Blo, K, N, bm, bn, (it + 1) * 32,
                        ar0, ar1, ak, br0, br1, bc);
            cp_commit();
            cp_wait1();
        } else {
            cp_wait0();
        }
        __syncthreads();

        unsigned int s0   = sbase + (unsigned int)cur * STAGE_BYTES;
        unsigned int sBhi = s0 + 2u * AS_BYTES;

#pragma unroll
        for (int ks = 0; ks < 2; ks++) {
            int k16 = ks * 16;
            unsigned int a_hi[4][4];
            unsigned int a_lo[4][4];
#pragma unroll
            for (int mi = 0; mi < 4; mi++) {
                unsigned int addr = s0 +
                    (unsigned int)((wm * 64 + mi * 16 + arow) * AST + k16 + acolh) * 2u;
                ldm_x4(a_hi[mi], addr);
                ldm_x4(a_lo[mi], addr + AS_BYTES);
            }
            unsigned int b_hi[2][4];
            unsigned int b_lo[2][4];
#pragma unroll
            for (int nj = 0; nj < 2; nj++) {
                unsigned int addr = sBhi +
                    (unsigned int)((k16 + arow) * BST + wn * 32 + nj * 16 + acolh) * 2u;
                ldm_x4t(b_hi[nj], addr);
                ldm_x4t(b_lo[nj], addr + BS_BYTES);
            }
#pragma unroll
            for (int mi = 0; mi < 4; mi++) {
#pragma unroll
                for (int nj = 0; nj < 2; nj++) {
                    mma16816(acc[mi][2 * nj],     a_hi[mi], b_hi[nj][0], b_hi[nj][1]);
                    mma16816(acc[mi][2 * nj + 1], a_hi[mi], b_hi[nj][2], b_hi[nj][3]);
                    mma16816(acc[mi][2 * nj],     a_hi[mi], b_lo[nj][0], b_lo[nj][1]);
                    mma16816(acc[mi][2 * nj + 1], a_hi[mi], b_lo[nj][2], b_lo[nj][3]);
                    mma16816(acc[mi][2 * nj],     a_lo[mi], b_hi[nj][0], b_hi[nj][1]);
                    mma16816(acc[mi][2 * nj + 1], a_lo[mi], b_hi[nj][2], b_hi[nj][3]);
                }
            }
        }
        __syncthreads();
    }

    const int r0 = bm + wm * 64;
    const int c0 = bn + wn * 32;
#pragma unroll
    for (int mi = 0; mi < 4; mi++) {
#pragma unroll
        for (int ng = 0; ng < 4; ng++) {
            int row = r0 + mi * 16 + (lane >> 2);
            int col = c0 + ng * 8 + (lane & 3) * 2;
            *(float2*)(C + (size_t)row * N + col) =
                make_float2(acc[mi][ng][0], acc[mi][ng][1]);
            *(float2*)(C + (size_t)(row + 8) * N + col) =
                make_float2(acc[mi][ng][2], acc[mi][ng][3]);
        }
    }
}

// ---------------------------------------------------------------------------
// RoPE + bf16 hi/lo split. Reads fp32 x, writes rotated (and scaled) hi/lo.
// grid = (rows, nheads), block = 64 threads (one per rotation pair).
// ---------------------------------------------------------------------------
__global__ __launch_bounds__(64) void rope_split(
    const float* __restrict__ x, __nv_bfloat16* __restrict__ hi,
    __nv_bfloat16* __restrict__ lo, int nheads, float scale)
{
    const int pair = threadIdx.x;
    const int h    = blockIdx.y;
    const int row  = blockIdx.x;
    const int s    = row % SEQ;

    double inv_d = exp(-(double)pair * (1.0 / 64.0) * log(10000.0));
    float  inv_f = (float)inv_d;
    float  ang_f = (float)s * inv_f;

    float c  = (float)cos((double)ang_f);
    float sn = (float)sin((double)ang_f);

    size_t off = (size_t)row * (nheads * HD) + h * HD + pair * 2;
    float x0 = x[off];
    float x1 = x[off + 1];
    float r0 = (x0 * c - x1 * sn) * scale;
    float r1 = (x0 * sn + x1 * c) * scale;

    __nv_bfloat16 h0 = __float2bfloat16(r0);
    __nv_bfloat16 h1 = __float2bfloat16(r1);
    hi[off]     = h0;
    hi[off + 1] = h1;
    lo[off]     = __float2bfloat16(r0 - __bfloat162float(h0));
    lo[off + 1] = __float2bfloat16(r1 - __bfloat162float(h1));
}

// ---------------------------------------------------------------------------
// Flash attention (bf16 mma, full hi/lo split on QK and PV, fp32 softmax).
// Block = (64-row q tile, head, batch). 4 warps. K-tiles of 32 keys,
// cp.async double-buffered. Warp w owns q rows [16w, 16w+16).
// ---------------------------------------------------------------------------
#define FST 136
#define FQ_BYTES (64 * FST * 2)          // 17408 per array
#define FK_BYTES (32 * FST * 2)          // 8704 per array
#define FSTAGE (4 * FK_BYTES)            // Kh,Kl,Vh,Vl
#define FA_SMEM (2 * FQ_BYTES + 2 * FSTAGE)   // 104448

__global__ __launch_bounds__(128) void flash_attn(
    const __nv_bfloat16* __restrict__ Qh, const __nv_bfloat16* __restrict__ Ql,
    const __nv_bfloat16* __restrict__ Kh, const __nv_bfloat16* __restrict__ Kl,
    const __nv_bfloat16* __restrict__ Vh, const __nv_bfloat16* __restrict__ Vl,
    float* __restrict__ O)
{
    extern __shared__ char smraw[];
    const int tid  = threadIdx.x;
    const int warp = tid >> 5;
    const int lane = tid & 31;
    const int qt   = blockIdx.x;
    const int h    = blockIdx.y;
    const int b    = blockIdx.z;
    const int g    = h >> 2;
    const int q0   = qt * 64;

    unsigned int sbase = (unsigned int)__cvta_generic_to_shared(smraw);
    unsigned int sQ    = sbase;                    // Qh then Ql (FQ_BYTES apart)
    unsigned int sKV   = sbase + 2u * FQ_BYTES;    // stage base

    // issue Q tile loads (part of cp group 0)
    {
        size_t rowb = (size_t)b * SEQ + q0;
        for (int i = tid; i < 1024; i += 128) {
            int r = i >> 4;
            int c = (i & 15) << 3;
            size_t goff = (rowb + r) * QSTR + h * HD + c;
            unsigned int d = sQ + (unsigned int)(r * FST + c) * 2u;
            cp16(d, Qh + goff);
            cp16(d + FQ_BYTES, Ql + goff);
        }
    }
    // issue K/V stage 0
    const int nkt = 2 * qt + 2;
    {
        size_t rowb = (size_t)b * SEQ;
        for (int i = tid; i < 512; i += 128) {
            int r = i >> 4;
            int c = (i & 15) << 3;
            size_t goff = (rowb + r) * KSTR + g * HD + c;
            unsigned int d = sKV + (unsigned int)(r * FST + c) * 2u;
            cp16(d, Kh + goff);
            cp16(d + FK_BYTES, Kl + goff);
            cp16(d + 2u * FK_BYTES, Vh + goff);
            cp16(d + 3u * FK_BYTES, Vl + goff);
        }
    }
    cp_commit();

    float oacc[16][4];
#pragma unroll
    for (int i = 0; i < 16; i++) {
#pragma unroll
        for (int j = 0; j < 4; j++) {
            oacc[i][j] = 0.0f;
        }
    }
    float sm0 = -INFINITY;
    float sm1 = -INFINITY;
    float sl0 = 0.0f;
    float sl1 = 0.0f;

    const int arow  = lane & 15;
    const int acolh = (lane >> 4) << 3;
    const int brow  = (lane & 7) | ((lane >> 1) & 8);   // QK B-frag row remap
    const int bcolh = ((lane >> 3) & 1) << 3;

    for (int kt = 0; kt < nkt; kt++) {
        int st = kt & 1;
        if (kt + 1 < nkt) {
            size_t rowb = (size_t)b * SEQ + (kt + 1) * 32;
            unsigned int sN = sKV + (unsigned int)(st ^ 1) * FSTAGE;
            for (int i = tid; i < 512; i += 128) {
                int r = i >> 4;
                int c = (i & 15) << 3;
                size_t goff = (rowb + r) * KSTR + g * HD + c;
                unsigned int d = sN + (unsigned int)(r * FST + c) * 2u;
                cp16(d, Kh + goff);
                cp16(d + FK_BYTES, Kl + goff);
                cp16(d + 2u * FK_BYTES, Vh + goff);
                cp16(d + 3u * FK_BYTES, Vl + goff);
            }
            cp_commit();
            cp_wait1();
        } else {
            cp_wait0();
        }
        __syncthreads();

        unsigned int pK = sKV + (unsigned int)st * FSTAGE;
        unsigned int pV = pK + 2u * FK_BYTES;

        // ---- scores: S = Q Kt^T  (16 rows x 32 keys per warp) ----
        float sacc[4][4];
#pragma unroll
        for (int i = 0; i < 4; i++) {
#pragma unroll
            for (int j = 0; j < 4; j++) {
                sacc[i][j] = 0.0f;
            }
        }
#pragma unroll
        for (int kk = 0; kk < 8; kk++) {
            unsigned int a_hi[4];
            unsigned int a_lo[4];
            unsigned int aaddr = sQ +
                (unsigned int)((warp * 16 + arow) * FST + kk * 16 + acolh) * 2u;
            ldm_x4(a_hi, aaddr);
            ldm_x4(a_lo, aaddr + FQ_BYTES);
#pragma unroll
            for (int ng = 0; ng < 2; ng++) {
                unsigned int b_hi[4];
                unsigned int b_lo[4];
                unsigned int baddr = pK +
                    (unsigned int)((ng * 16 + brow) * FST + kk * 16 + bcolh) * 2u;
                ldm_x4(b_hi, baddr);
                ldm_x4(b_lo, baddr + FK_BYTES);
                mma16816(sacc[2 * ng],     a_hi, b_hi[0], b_hi[1]);
                mma16816(sacc[2 * ng],     a_hi, b_lo[0], b_lo[1]);
                mma16816(sacc[2 * ng],     a_lo, b_hi[0], b_hi[1]);
                mma16816(sacc[2 * ng + 1], a_hi, b_hi[2], b_hi[3]);
                mma16816(sacc[2 * ng + 1], a_hi, b_lo[2], b_lo[3]);
                mma16816(sacc[2 * ng + 1], a_lo, b_hi[2], b_hi[3]);
            }
        }

        // ---- causal mask on diagonal tiles ----
        int k0 = kt * 32;
        if (kt >= 2 * qt) {
#pragma unroll
            for (int nt = 0; nt < 4; nt++) {
#pragma unroll
                for (int c = 0; c < 4; c++) {
                    int kg = k0 + nt * 8 + ((lane & 3) << 1) + (c & 1);
                    int qg = q0 + warp * 16 + (lane >> 2) + ((c >> 1) << 3);
                    if (kg > qg) {
                        sacc[nt][c] = -INFINITY;
                    }
                }
            }
        }

        // ---- online softmax (rows rA = lane>>2, rB = rA+8) ----
        float tm0 = -INFINITY;
        float tm1 = -INFINITY;
#pragma unroll
        for (int nt = 0; nt < 4; nt++) {
            tm0 = fmaxf(tm0, fmaxf(sacc[nt][0], sacc[nt][1]));
            tm1 = fmaxf(tm1, fmaxf(sacc[nt][2], sacc[nt][3]));
        }
        tm0 = fmaxf(tm0, __shfl_xor_sync(0xFFFFFFFFu, tm0, 1));
        tm0 = fmaxf(tm0, __shfl_xor_sync(0xFFFFFFFFu, tm0, 2));
        tm1 = fmaxf(tm1, __shfl_xor_sync(0xFFFFFFFFu, tm1, 1));
        tm1 = fmaxf(tm1, __shfl_xor_sync(0xFFFFFFFFu, tm1, 2));

        float mn0 = fmaxf(sm0, tm0);
        float mn1 = fmaxf(sm1, tm1);
        float al0 = expf(sm0 - mn0);
        float al1 = expf(sm1 - mn1);
        sm0 = mn0;
        sm1 = mn1;

        float rs0 = 0.0f;
        float rs1 = 0.0f;
#pragma unroll
        for (int nt = 0; nt < 4; nt++) {
            float p0 = expf(sacc[nt][0] - mn0);
            float p1 = expf(sacc[nt][1] - mn0);
            float p2 = expf(sacc[nt][2] - mn1);
            float p3 = expf(sacc[nt][3] - mn1);
            sacc[nt][0] = p0;
            sacc[nt][1] = p1;
            sacc[nt][2] = p2;
            sacc[nt][3] = p3;
            rs0 += p0 + p1;
            rs1 += p2 + p3;
        }
        rs0 += __shfl_xor_sync(0xFFFFFFFFu, rs0, 1);
        rs0 += __shfl_xor_sync(0xFFFFFFFFu, rs0, 2);
        rs1 += __shfl_xor_sync(0xFFFFFFFFu, rs1, 1);
        rs1 += __shfl_xor_sync(0xFFFFFFFFu, rs1, 2);
        sl0 = sl0 * al0 + rs0;
        sl1 = sl1 * al1 + rs1;

#pragma unroll
        for (int nt = 0; nt < 16; nt++) {
            oacc[nt][0] *= al0;
            oacc[nt][1] *= al0;
            oacc[nt][2] *= al1;
            oacc[nt][3] *= al1;
        }

        // ---- PV: O += P V  (P 16x32, V 32x128) ----
#pragma unroll
        for (int ks = 0; ks < 2; ks++) {
            int ntA = 2 * ks;
            int ntB = 2 * ks + 1;
            unsigned int ap_hi[4];
            unsigned int ap_lo[4];
            {
                float pa0 = sacc[ntA][0];
                float pa1 = sacc[ntA][1];
                float ha0 = __bfloat162float(__float2bfloat16(pa0));
                float ha1 = __bfloat162float(__float2bfloat16(pa1));
                ap_hi[0] = pack_bf2(ha0, ha1);
                ap_lo[0] = pack_bf2(pa0 - ha0, pa1 - ha1);
                float pb0 = sacc[ntA][2];
                float pb1 = sacc[ntA][3];
                float hb0 = __bfloat162float(__float2bfloat16(pb0));
                float hb1 = __bfloat162float(__float2bfloat16(pb1));
                ap_hi[1] = pack_bf2(hb0, hb1);
                ap_lo[1] = pack_bf2(pb0 - hb0, pb1 - hb1);
                float pc0 = sacc[ntB][0];
                float pc1 = sacc[ntB][1];
                float hc0 = __bfloat162float(__float2bfloat16(pc0));
                float hc1 = __bfloat162float(__float2bfloat16(pc1));
                ap_hi[2] = pack_bf2(hc0, hc1);
                ap_lo[2] = pack_bf2(pc0 - hc0, pc1 - hc1);
                float pd0 = sacc[ntB][2];
                float pd1 = sacc[ntB][3];
                float hd0 = __bfloat162float(__float2bfloat16(pd0));
                float hd1 = __bfloat162float(__float2bfloat16(pd1));
                ap_hi[3] = pack_bf2(hd0, hd1);
                ap_lo[3] = pack_bf2(pd0 - hd0, pd1 - hd1);
            }
#pragma unroll
            for (int nt2 = 0; nt2 < 8; nt2++) {
                unsigned int b_hi[4];
                unsigned int b_lo[4];
                unsigned int baddr = pV +
                    (unsigned int)((ks * 16 + arow) * FST + nt2 * 16 + acolh) * 2u;
                ldm_x4t(b_hi, baddr);
                ldm_x4t(b_lo, baddr + FK_BYTES);
                mma16816(oacc[2 * nt2],     ap_hi, b_hi[0], b_hi[1]);
                mma16816(oacc[2 * nt2],     ap_hi, b_lo[0], b_lo[1]);
                mma16816(oacc[2 * nt2],     ap_lo, b_hi[0], b_hi[1]);
                mma16816(oacc[2 * nt2 + 1], ap_hi, b_hi[2], b_hi[3]);
                mma16816(oacc[2 * nt2 + 1], ap_hi, b_lo[2], b_lo[3]);
                mma16816(oacc[2 * nt2 + 1], ap_lo, b_hi[2], b_hi[3]);
            }
        }
        __syncthreads();
    }

    // ---- epilogue ----
    float i0 = 1.0f / sl0;
    float i1 = 1.0f / sl1;
    int rg = q0 + warp * 16 + (lane >> 2);
    size_t orow0 = ((size_t)b * SEQ + rg) * QSTR + h * HD;
    size_t orow1 = orow0 + (size_t)8 * QSTR;
#pragma unroll
    for (int nt = 0; nt < 16; nt++) {
        int col = nt * 8 + ((lane & 3) << 1);
        *(float2*)(O + orow0 + col) = make_float2(oacc[nt][0] * i0, oacc[nt][1] * i0);
        *(float2*)(O + orow1 + col) = make_float2(oacc[nt][2] * i1, oacc[nt][3] * i1);
    }
}

// ---------------------------------------------------------------------------
extern "C" void kernel_launch(void* const* d_in, const int* in_sizes, int n_in,
                              void* d_out, int out_size)
{
    const float* x;
    const float* wq;
    const float* wk;
    const float* wv;
    const float* wo;
    if (n_in >= 7 && in_sizes[0] == 1 && in_sizes[1] == 1) {
        if (in_sizes[2] == 16777216) {
            x  = (const float*)d_in[2];
            wq = (const float*)d_in[3];
            wk = (const float*)d_in[4];
            wv = (const float*)d_in[5];
            wo = (const float*)d_in[6];
        } else {
            wk = (const float*)d_in[2];
            wo = (const float*)d_in[3];
            wq = (const float*)d_in[4];
            wv = (const float*)d_in[5];
            x  = (const float*)d_in[6];
        }
    } else {
        x  = (const float*)d_in[0];
        wq = (const float*)d_in[1];
        wk = (const float*)d_in[2];
        wv = (const float*)d_in[3];
        wo = (const float*)d_in[4];
    }
    float* out = (float*)d_out;

    float* Qp;
    float* Kp;
    float* Vp;
    float* Op;
    cudaGetSymbolAddress((void**)&Qp, g_Q);
    cudaGetSymbolAddress((void**)&Kp, g_K);
    cudaGetSymbolAddress((void**)&Vp, g_V);
    cudaGetSymbolAddress((void**)&Op, g_O);

    __nv_bfloat16* xh;
    __nv_bfloat16* xl;
    __nv_bfloat16* qh;
    __nv_bfloat16* ql;
    __nv_bfloat16* kh;
    __nv_bfloat16* kl;
    __nv_bfloat16* vh;
    __nv_bfloat16* vl;
    __nv_bfloat16* oh;
    __nv_bfloat16* ol;
    __nv_bfloat16* ph;
    __nv_bfloat16* pl;
    cudaGetSymbolAddress((void**)&xh, g_x_hi);
    cudaGetSymbolAddress((void**)&xl, g_x_lo);
    cudaGetSymbolAddress((void**)&qh, g_wq_hi);
    cudaGetSymbolAddress((void**)&ql, g_wq_lo);
    cudaGetSymbolAddress((void**)&kh, g_wk_hi);
    cudaGetSymbolAddress((void**)&kl, g_wk_lo);
    cudaGetSymbolAddress((void**)&vh, g_wv_hi);
    cudaGetSymbolAddress((void**)&vl, g_wv_lo);
    cudaGetSymbolAddress((void**)&oh, g_wo_hi);
    cudaGetSymbolAddress((void**)&ol, g_wo_lo);
    cudaGetSymbolAddress((void**)&ph, g_o_hi);
    cudaGetSymbolAddress((void**)&pl, g_o_lo);

    __nv_bfloat16* qbh;
    __nv_bfloat16* qbl;
    __nv_bfloat16* kbh;
    __nv_bfloat16* kbl;
    __nv_bfloat16* vbh;
    __nv_bfloat16* vbl;
    cudaGetSymbolAddress((void**)&qbh, g_qb_hi);
    cudaGetSymbolAddress((void**)&qbl, g_qb_lo);
    cudaGetSymbolAddress((void**)&kbh, g_kb_hi);
    cudaGetSymbolAddress((void**)&kbl, g_kb_lo);
    cudaGetSymbolAddress((void**)&vbh, g_vb_hi);
    cudaGetSymbolAddress((void**)&vbl, g_vb_lo);

    const int M = MROWS;

    const int n1 = M * DMODEL;
    const int n2 = DMODEL * DMODEL;
    const int n3 = DMODEL * KSTR;
    cvt_split<<<n1 / 1024, 256>>>(x,  xh, xl, n1);
    cvt_split<<<n2 / 1024, 256>>>(wq, qh, ql, n2);
    cvt_split<<<n3 / 1024, 256>>>(wk, kh, kl, n3);
    cvt_split<<<n3 / 1024, 256>>>(wv, vh, vl, n3);
    cvt_split<<<n2 / 1024, 256>>>(wo, oh, ol, n2);

    cudaFuncSetAttribute(gemm_bf16x3,
                         cudaFuncAttributeMaxDynamicSharedMemorySize, GEMM_SMEM);
    cudaFuncSetAttribute(flash_attn,
                         cudaFuncAttributeMaxDynamicSharedMemorySize, FA_SMEM);

    gemm_bf16x3<<<dim3(DMODEL / 128, M / 128), 256, GEMM_SMEM>>>(
        xh, xl, qh, ql, Qp, M, DMODEL, DMODEL);
    gemm_bf16x3<<<dim3(KSTR / 128, M / 128), 256, GEMM_SMEM>>>(
        xh, xl, kh, kl, Kp, M, KSTR, DMODEL);
    gemm_bf16x3<<<dim3(KSTR / 128, M / 128), 256, GEMM_SMEM>>>(
        xh, xl, vh, vl, Vp, M, KSTR, DMODEL);

    // RoPE + split (scale folded into Q); V split
    const float scale = 0.08838834764831845f;  // 1/sqrt(128)
    rope_split<<<dim3(M, NH), 64>>>(Qp, qbh, qbl, NH, scale);
    rope_split<<<dim3(M, NKV), 64>>>(Kp, kbh, kbl, NKV, 1.0f);
    cvt_split<<<(M * KSTR) / 1024, 256>>>(Vp, vbh, vbl, M * KSTR);

    // Flash attention (tensor cores)
    flash_attn<<<dim3(SEQ / 64, NH, BSZ), 128, FA_SMEM>>>(
        qbh, qbl, kbh, kbl, vbh, vbl, Op);

    // O projection
    cvt_split<<<(M * DMODEL) / 1024, 256>>>(Op, ph, pl, M * DMODEL);
    gemm_bf16x3<<<dim3(DMODEL / 128, M / 128), 256, GEMM_SMEM>>>(
        ph, pl, oh, ol, out, M, DMODEL, DMODEL);
}